// round 7
// baseline (speedup 1.0000x reference)
#include <cuda_runtime.h>
#include <cstdint>

#define Bq 8
#define Cc 256
#define NQ 4096
#define NK 4096
#define KK 8
#define SPLIT 4
#define KPB (NK / SPLIT)     // 1024 keys per knn block

// Scratch (device globals — no allocation allowed)
__device__ float g_kf_t[(size_t)Bq * NK * Cc];   // key_features transposed [b, m, c]
__device__ float g_qf_t[(size_t)Bq * NQ * Cc];   // query_features transposed [b, n, c]
__device__ int   g_idx[(size_t)Bq * NQ * KK];    // merged knn indices
__device__ float g_pd[(size_t)SPLIT * Bq * NQ * KK];  // partial top-8 distances
__device__ int   g_pi[(size_t)SPLIT * Bq * NQ * KK];  // partial top-8 indices

// ---------------------------------------------------------------------------
// Transpose [B, C, N] -> [B, N, C]   (N = 4096, C = 256)
// ---------------------------------------------------------------------------
__global__ void transpose_kernel(const float* __restrict__ in, float* __restrict__ out) {
    __shared__ float tile[32][33];
    const int b  = blockIdx.z;
    const int n0 = blockIdx.x * 32;
    const int c0 = blockIdx.y * 32;
    const float* inb  = in  + (size_t)b * Cc * NQ;
    float*       outb = out + (size_t)b * Cc * NQ;
    const int tx = threadIdx.x;   // 0..31
    const int ty = threadIdx.y;   // 0..7
#pragma unroll
    for (int j = 0; j < 32; j += 8)
        tile[ty + j][tx] = inb[(size_t)(c0 + ty + j) * NQ + (n0 + tx)];
    __syncthreads();
#pragma unroll
    for (int j = 0; j < 32; j += 8)
        outb[(size_t)(n0 + ty + j) * Cc + (c0 + tx)] = tile[tx][ty + j];
}

// ---------------------------------------------------------------------------
// kNN, split-K: each block scans KPB keys for 256 queries; writes a sorted
// partial top-8 (d,i). Arithmetic is the verified bitwise tree:
//   cross = fma(qz,kz, fma(qy,ky, rn(qx*kx)))   sq/sk same fma-ascending
//   d     = rn(rn(sq - 2*cross) + sk)
// ---------------------------------------------------------------------------
__global__ void __launch_bounds__(256, 4)
knn_kernel(const float* __restrict__ qc, const float* __restrict__ kc) {
    __shared__ float4 skey[KPB];   // 16 KB: (kx, ky, kz, |k|^2)

    const int b  = blockIdx.x / (NQ / 256);
    const int n0 = (blockIdx.x % (NQ / 256)) * 256;
    const int s  = blockIdx.y;
    const int kbase = s * KPB;
    const int n  = n0 + threadIdx.x;

    const float* kcb = kc + (size_t)b * 3 * NK;
    const float* qcb = qc + (size_t)b * 3 * NQ;

    const float qx = qcb[n];
    const float qy = qcb[NQ + n];
    const float qz = qcb[2 * NQ + n];
    const float sq = fmaf(qz, qz, fmaf(qy, qy, __fmul_rn(qx, qx)));

    // stage keys (coalesced per coordinate plane)
    for (int m = threadIdx.x; m < KPB; m += 256) {
        const int gm = kbase + m;
        const float x = kcb[gm];
        const float y = kcb[NK + gm];
        const float z = kcb[2 * NK + gm];
        const float skk = fmaf(z, z, fmaf(y, y, __fmul_rn(x, x)));
        skey[m] = make_float4(x, y, z, skk);
    }
    __syncthreads();

    float bd[KK];
    int   bi[KK];
#pragma unroll
    for (int j = 0; j < KK; j++) { bd[j] = 3.4e38f; bi[j] = 0; }

    for (int m = 0; m < KPB; m += 4) {
#pragma unroll
        for (int u = 0; u < 4; u++) {
            const float4 kv = skey[m + u];            // uniform addr -> broadcast
            const float cross = fmaf(qz, kv.z,
                                fmaf(qy, kv.y,
                                     __fmul_rn(qx, kv.x)));
            const float t = __fadd_rn(sq, -2.0f * cross);
            const float d = __fadd_rn(t, kv.w);
            if (d < bd[KK - 1]) {                     // rare
                float cd = d; int ci = kbase + m + u;
#pragma unroll
                for (int j = 0; j < KK; j++) {
                    const bool sw = cd < bd[j];
                    const float td = bd[j]; const int ti = bi[j];
                    bd[j] = sw ? cd : td;  bi[j] = sw ? ci : ti;
                    cd    = sw ? td : cd;  ci    = sw ? ti : ci;
                }
            }
        }
    }

    const size_t o = (((size_t)s * Bq + b) * NQ + n) * KK;
#pragma unroll
    for (int j = 0; j < KK; j++) { g_pd[o + j] = bd[j]; g_pi[o + j] = bi[j]; }
}

// ---------------------------------------------------------------------------
// Merge SPLIT sorted 8-lists -> final top-8. Splits processed in ascending
// order (ascending key index ranges), lists ascending-d with ties in index
// order, strict '<' insertion => identical tie-break to lax.top_k.
// ---------------------------------------------------------------------------
__global__ void __launch_bounds__(256)
merge_kernel() {
    const int g = blockIdx.x * 256 + threadIdx.x;   // 0 .. Bq*NQ-1
    float bd[KK];
    int   bi[KK];
#pragma unroll
    for (int j = 0; j < KK; j++) { bd[j] = 3.4e38f; bi[j] = 0; }

#pragma unroll
    for (int s = 0; s < SPLIT; s++) {
        const size_t o = ((size_t)s * Bq * NQ + g) * KK;
#pragma unroll
        for (int j = 0; j < KK; j++) {
            const float d = g_pd[o + j];
            if (d < bd[KK - 1]) {
                float cd = d; int ci = g_pi[o + j];
#pragma unroll
                for (int l = 0; l < KK; l++) {
                    const bool sw = cd < bd[l];
                    const float td = bd[l]; const int ti = bi[l];
                    bd[l] = sw ? cd : td;  bi[l] = sw ? ci : ti;
                    cd    = sw ? td : cd;  ci    = sw ? ti : ci;
                }
            }
        }
    }

    int* o = g_idx + (size_t)g * KK;
#pragma unroll
    for (int j = 0; j < KK; j++) o[j] = bi[j];
}

// ---------------------------------------------------------------------------
// Gather + concat. Block = 4 queries x 8 neighbors = 32 slots.
// Stage 32 neighbor rows (1KB each, contiguous from g_kf_t) + 4 query rows
// in padded smem, then write float4-coalesced to out[b, 2C, NQ, K].
// ---------------------------------------------------------------------------
#define NT 4
#define SLOTS (NT * KK)      // 32
#define PADN 257
#define PADQ 260

__global__ void __launch_bounds__(256, 5)
gather_kernel(float* __restrict__ out) {
    __shared__ int   sidx[SLOTS];
    __shared__ float sn[SLOTS * PADN];   // ~32.9 KB
    __shared__ float sq[NT * PADQ];      // ~4.1 KB

    const int b  = blockIdx.x / (NQ / NT);
    const int n0 = (blockIdx.x % (NQ / NT)) * NT;
    const int t  = threadIdx.x;

    if (t < SLOTS)
        sidx[t] = g_idx[((size_t)b * NQ + n0) * KK + t];

    // stage query rows [NT][C]
    for (int i = t; i < NT * Cc; i += 256) {
        const int r = i >> 8;           // /C
        const int c = i & (Cc - 1);
        sq[r * PADQ + c] = g_qf_t[((size_t)b * NQ + n0 + r) * Cc + c];
    }
    __syncthreads();

    // gather neighbor rows: 32 x 1KB coalesced loads
#pragma unroll
    for (int r = 0; r < SLOTS; r++) {
        sn[r * PADN + t] = g_kf_t[((size_t)b * NK + sidx[r]) * Cc + t];
    }
    __syncthreads();

    // write phase: thread owns slot quad q (slots 4q..4q+3, one query each)
    // and channel group cg; STG.128 stores, conflict-free sn reads.
    const int q  = t & 7;               // slot quad 0..7
    const int cg = t >> 3;              // 0..31
    const int s0 = 4 * q;
    const int nloc = q >> 1;            // local query index (quad within query)

#pragma unroll
    for (int ci = 0; ci < 8; ci++) {
        const int c = ci * 32 + cg;
        const float qv = sq[nloc * PADQ + c];
        const float v0 = sn[(s0 + 0) * PADN + c];
        const float v1 = sn[(s0 + 1) * PADN + c];
        const float v2 = sn[(s0 + 2) * PADN + c];
        const float v3 = sn[(s0 + 3) * PADN + c];

        const size_t baseD = (((size_t)b * (2 * Cc) + c) * NQ + n0) * KK + s0;
        const size_t baseQ = (((size_t)b * (2 * Cc) + Cc + c) * NQ + n0) * KK + s0;
        *reinterpret_cast<float4*>(out + baseD) =
            make_float4(v0 - qv, v1 - qv, v2 - qv, v3 - qv);
        *reinterpret_cast<float4*>(out + baseQ) = make_float4(qv, qv, qv, qv);
    }
}

// ---------------------------------------------------------------------------
extern "C" void kernel_launch(void* const* d_in, const int* in_sizes, int n_in,
                              void* d_out, int out_size) {
    const float* query_coords   = (const float*)d_in[0];
    const float* query_features = (const float*)d_in[1];
    const float* key_coords     = (const float*)d_in[2];
    const float* key_features   = (const float*)d_in[3];
    float* out = (float*)d_out;

    float* kf_t; cudaGetSymbolAddress((void**)&kf_t, g_kf_t);
    float* qf_t; cudaGetSymbolAddress((void**)&qf_t, g_qf_t);

    dim3 tgrid(NQ / 32, Cc / 32, Bq);
    dim3 tblk(32, 8);
    transpose_kernel<<<tgrid, tblk>>>(query_features, qf_t);
    transpose_kernel<<<tgrid, tblk>>>(key_features,   kf_t);

    dim3 kgrid(Bq * (NQ / 256), SPLIT);
    knn_kernel<<<kgrid, 256>>>(query_coords, key_coords);
    merge_kernel<<<Bq * NQ / 256, 256>>>();

    gather_kernel<<<Bq * (NQ / NT), 256>>>(out);
}